// round 4
// baseline (speedup 1.0000x reference)
#include <cuda_runtime.h>

// Single-kernel deterministic sum over three fp32 arrays.
// Grid is partitioned by array (work-proportional). Each block grid-strides
// its partition with an 8x-unrolled float4 loop (8 independent LDG.128 in
// flight per thread). ~4 CTAs/SM so ptxas has ~60 regs/thread for the MLP.
// Last block (int-counter threadfence pattern) reduces partials -> d_out.

#define NT 256
#define BLK_A 451
#define BLK_B 113
#define BLK_C 28
#define NBLK (BLK_A + BLK_B + BLK_C)   // 592 = 148 SMs x 4

__device__ float g_partials[NBLK];
__device__ unsigned int g_count = 0;

__device__ __forceinline__ float warp_reduce(float v) {
    #pragma unroll
    for (int off = 16; off > 0; off >>= 1)
        v += __shfl_down_sync(0xFFFFFFFFu, v, off);
    return v;
}

__global__ __launch_bounds__(NT) void sum3_part(
    const float4* __restrict__ a, int na4,
    const float4* __restrict__ b, int nb4,
    const float4* __restrict__ c, int nc4,
    float* __restrict__ out)
{
    // Select partition.
    const float4* __restrict__ p;
    int n4, lb, nb;
    if (blockIdx.x < BLK_A) {
        p = a; n4 = na4; lb = blockIdx.x;                 nb = BLK_A;
    } else if (blockIdx.x < BLK_A + BLK_B) {
        p = b; n4 = nb4; lb = blockIdx.x - BLK_A;         nb = BLK_B;
    } else {
        p = c; n4 = nc4; lb = blockIdx.x - BLK_A - BLK_B; nb = BLK_C;
    }

    const int tid    = lb * NT + threadIdx.x;
    const int stride = nb * NT;

    float s0 = 0.f, s1 = 0.f, s2 = 0.f, s3 = 0.f;
    float s4 = 0.f, s5 = 0.f, s6 = 0.f, s7 = 0.f;

    int i = tid;
    // Main loop: 8 independent 128-bit loads batched at the front.
    for (; i + 7 * stride < n4; i += 8 * stride) {
        float4 v0 = __ldg(p + i);
        float4 v1 = __ldg(p + i + 1 * stride);
        float4 v2 = __ldg(p + i + 2 * stride);
        float4 v3 = __ldg(p + i + 3 * stride);
        float4 v4 = __ldg(p + i + 4 * stride);
        float4 v5 = __ldg(p + i + 5 * stride);
        float4 v6 = __ldg(p + i + 6 * stride);
        float4 v7 = __ldg(p + i + 7 * stride);
        s0 += (v0.x + v0.y) + (v0.z + v0.w);
        s1 += (v1.x + v1.y) + (v1.z + v1.w);
        s2 += (v2.x + v2.y) + (v2.z + v2.w);
        s3 += (v3.x + v3.y) + (v3.z + v3.w);
        s4 += (v4.x + v4.y) + (v4.z + v4.w);
        s5 += (v5.x + v5.y) + (v5.z + v5.w);
        s6 += (v6.x + v6.y) + (v6.z + v6.w);
        s7 += (v7.x + v7.y) + (v7.z + v7.w);
    }
    // Tail.
    for (; i < n4; i += stride) {
        float4 v = __ldg(p + i);
        s0 += (v.x + v.y) + (v.z + v.w);
    }

    float s = ((s0 + s1) + (s2 + s3)) + ((s4 + s5) + (s6 + s7));

    // Block reduce.
    __shared__ float sh[NT / 32];
    s = warp_reduce(s);
    const int lane = threadIdx.x & 31;
    const int wid  = threadIdx.x >> 5;
    if (lane == 0) sh[wid] = s;
    __syncthreads();
    if (wid == 0) {
        float v = (lane < NT / 32) ? sh[lane] : 0.f;
        v = warp_reduce(v);
        if (lane == 0) g_partials[blockIdx.x] = v;
    }

    // Last-block-done detection (int counter -> deterministic).
    __shared__ bool is_last;
    if (threadIdx.x == 0) {
        __threadfence();
        unsigned int done = atomicAdd(&g_count, 1u);
        is_last = (done == (unsigned)(gridDim.x - 1));
    }
    __syncthreads();

    if (is_last) {
        float t = 0.f;
        for (int k = threadIdx.x; k < NBLK; k += NT)
            t += __ldcg(&g_partials[k]);      // fresh from L2
        t = warp_reduce(t);
        if (lane == 0) sh[wid] = t;
        __syncthreads();
        if (wid == 0) {
            float v = (lane < NT / 32) ? sh[lane] : 0.f;
            v = warp_reduce(v);
            if (lane == 0) {
                out[0] = v;
                g_count = 0;                  // reset for graph replay
            }
        }
    }
}

extern "C" void kernel_launch(void* const* d_in, const int* in_sizes, int n_in,
                              void* d_out, int out_size)
{
    const float4* a = (const float4*)d_in[0];
    const float4* b = (const float4*)d_in[1];
    const float4* c = (const float4*)d_in[2];
    const int na4 = in_sizes[0] / 4;
    const int nb4 = in_sizes[1] / 4;
    const int nc4 = in_sizes[2] / 4;

    sum3_part<<<NBLK, NT>>>(a, na4, b, nb4, c, nc4, (float*)d_out);
}

// round 6
// speedup vs baseline: 1.0526x; 1.0526x over previous
#include <cuda_runtime.h>
#include <cstdint>

// TMA-bulk streaming reduction over three fp32 arrays.
// Each block owns a contiguous chunk of one array. Data is staged
// global->SMEM via cp.async.bulk (bypasses the per-SM L1tex wavefront
// queue that caps LDG streaming at ~32KB in flight/SM), 4 stages x 16KB,
// 2 CTAs/SM. Consumers reduce from SMEM. Deterministic: fixed tile order,
// fixed per-thread accumulation, int-counter last-block final reduce.

#define NT 256
#define BLK_A 226
#define BLK_B 56
#define BLK_C 14
#define NBLK (BLK_A + BLK_B + BLK_C)    // 296 = 148 SMs x 2
#define STAGES 4
#define TILE4 1024                       // float4 per tile = 16KB
#define TILE_BYTES (TILE4 * 16)
#define SMEM_BYTES (STAGES * TILE_BYTES + STAGES * 8)

__device__ float g_partials[NBLK];
__device__ unsigned int g_count = 0;

__device__ __forceinline__ uint32_t smem_u32(const void* p) {
    uint32_t a;
    asm("{ .reg .u64 t; cvta.to.shared.u64 t, %1; cvt.u32.u64 %0, t; }"
        : "=r"(a) : "l"(p));
    return a;
}

__device__ __forceinline__ void mbar_init(uint32_t bar, uint32_t cnt) {
    asm volatile("mbarrier.init.shared.b64 [%0], %1;" :: "r"(bar), "r"(cnt) : "memory");
}

__device__ __forceinline__ void mbar_expect_tx(uint32_t bar, uint32_t bytes) {
    asm volatile("mbarrier.arrive.expect_tx.shared.b64 _, [%0], %1;"
                 :: "r"(bar), "r"(bytes) : "memory");
}

__device__ __forceinline__ void bulk_g2s(uint32_t dst, const void* src,
                                         uint32_t bytes, uint32_t bar) {
    asm volatile(
        "cp.async.bulk.shared::cta.global.mbarrier::complete_tx::bytes "
        "[%0], [%1], %2, [%3];"
        :: "r"(dst), "l"(src), "r"(bytes), "r"(bar) : "memory");
}

__device__ __forceinline__ void mbar_wait(uint32_t bar, uint32_t parity) {
    uint32_t done;
    asm volatile(
        "{\n\t.reg .pred p;\n\t"
        "mbarrier.try_wait.parity.acquire.cta.shared::cta.b64 p, [%1], %2;\n\t"
        "selp.b32 %0, 1, 0, p;\n\t}"
        : "=r"(done) : "r"(bar), "r"(parity) : "memory");
    if (!done) {
        asm volatile(
            "{\n\t.reg .pred P1;\n\t"
            "W_%=:\n\t"
            "mbarrier.try_wait.parity.acquire.cta.shared::cta.b64 P1, [%0], %1, 0x989680;\n\t"
            "@P1 bra.uni D_%=;\n\t"
            "bra.uni W_%=;\n\t"
            "D_%=:\n\t}"
            :: "r"(bar), "r"(parity) : "memory");
    }
}

__device__ __forceinline__ float warp_reduce(float v) {
    #pragma unroll
    for (int off = 16; off > 0; off >>= 1)
        v += __shfl_down_sync(0xFFFFFFFFu, v, off);
    return v;
}

__global__ __launch_bounds__(NT, 2) void sum3_tma(
    const float4* __restrict__ a, int na4,
    const float4* __restrict__ b, int nb4,
    const float4* __restrict__ c, int nc4,
    float* __restrict__ out)
{
    extern __shared__ __align__(128) unsigned char smem[];
    const float4* __restrict__ buf = (const float4*)smem;
    const uint32_t smem_base = smem_u32(smem);
    const uint32_t bar_base  = smem_base + STAGES * TILE_BYTES;

    // Partition select: contiguous chunk of one array per block.
    const float4* __restrict__ p;
    int n4, lb, nb;
    if (blockIdx.x < BLK_A) {
        p = a; n4 = na4; lb = blockIdx.x;                 nb = BLK_A;
    } else if (blockIdx.x < BLK_A + BLK_B) {
        p = b; n4 = nb4; lb = blockIdx.x - BLK_A;         nb = BLK_B;
    } else {
        p = c; n4 = nc4; lb = blockIdx.x - BLK_A - BLK_B; nb = BLK_C;
    }
    const int chunk = (n4 + nb - 1) / nb;
    const int c0    = lb * chunk;
    const int cn    = (n4 - c0 < chunk) ? (n4 - c0) : chunk;   // >0 by construction
    const int ntiles = (cn + TILE4 - 1) / TILE4;

    if (threadIdx.x == 0) {
        #pragma unroll
        for (int s = 0; s < STAGES; s++) mbar_init(bar_base + 8u * s, 1);
    }
    __syncthreads();

    // Prologue: fill the pipeline.
    if (threadIdx.x == 0) {
        const int pre = (ntiles < STAGES) ? ntiles : STAGES;
        for (int t = 0; t < pre; t++) {
            const int off   = t * TILE4;
            const int tn    = (cn - off >= TILE4) ? TILE4 : (cn - off);
            const uint32_t bytes = (uint32_t)tn * 16u;
            mbar_expect_tx(bar_base + 8u * t, bytes);
            bulk_g2s(smem_base + (uint32_t)t * TILE_BYTES, p + c0 + off, bytes,
                     bar_base + 8u * t);
        }
    }

    float s0 = 0.f, s1 = 0.f, s2 = 0.f, s3 = 0.f;
    const int tx = threadIdx.x;

    for (int t = 0; t < ntiles; t++) {
        const int s  = t & (STAGES - 1);
        const uint32_t ph = (uint32_t)(t / STAGES) & 1u;
        mbar_wait(bar_base + 8u * s, ph);

        const int off = t * TILE4;
        const int tn  = (cn - off >= TILE4) ? TILE4 : (cn - off);
        const float4* __restrict__ tb = buf + s * TILE4;

        if (tn == TILE4) {
            float4 v0 = tb[tx];
            float4 v1 = tb[tx + NT];
            float4 v2 = tb[tx + 2 * NT];
            float4 v3 = tb[tx + 3 * NT];
            s0 += (v0.x + v0.y) + (v0.z + v0.w);
            s1 += (v1.x + v1.y) + (v1.z + v1.w);
            s2 += (v2.x + v2.y) + (v2.z + v2.w);
            s3 += (v3.x + v3.y) + (v3.z + v3.w);
        } else {
            #pragma unroll
            for (int k = 0; k < 4; k++) {
                const int j = tx + k * NT;
                if (j < tn) {
                    float4 v = tb[j];
                    s0 += (v.x + v.y) + (v.z + v.w);
                }
            }
        }
        __syncthreads();   // slot s fully consumed by all threads

        if (threadIdx.x == 0 && t + STAGES < ntiles) {
            const int o2 = (t + STAGES) * TILE4;
            const int t2 = (cn - o2 >= TILE4) ? TILE4 : (cn - o2);
            const uint32_t bytes = (uint32_t)t2 * 16u;
            mbar_expect_tx(bar_base + 8u * s, bytes);
            bulk_g2s(smem_base + (uint32_t)s * TILE_BYTES, p + c0 + o2, bytes,
                     bar_base + 8u * s);
        }
    }

    float s = (s0 + s1) + (s2 + s3);

    // Block reduce.
    __shared__ float sh[NT / 32];
    s = warp_reduce(s);
    const int lane = threadIdx.x & 31;
    const int wid  = threadIdx.x >> 5;
    if (lane == 0) sh[wid] = s;
    __syncthreads();
    if (wid == 0) {
        float v = (lane < NT / 32) ? sh[lane] : 0.f;
        v = warp_reduce(v);
        if (lane == 0) g_partials[blockIdx.x] = v;
    }

    // Last-block-done detection (int counter -> deterministic).
    __shared__ bool is_last;
    if (threadIdx.x == 0) {
        __threadfence();
        unsigned int done = atomicAdd(&g_count, 1u);
        is_last = (done == (unsigned)(gridDim.x - 1));
    }
    __syncthreads();

    if (is_last) {
        float t = 0.f;
        for (int k = threadIdx.x; k < NBLK; k += NT)
            t += __ldcg(&g_partials[k]);
        t = warp_reduce(t);
        if (lane == 0) sh[wid] = t;
        __syncthreads();
        if (wid == 0) {
            float v = (lane < NT / 32) ? sh[lane] : 0.f;
            v = warp_reduce(v);
            if (lane == 0) {
                out[0] = v;
                g_count = 0;   // reset for graph replay
            }
        }
    }
}

extern "C" void kernel_launch(void* const* d_in, const int* in_sizes, int n_in,
                              void* d_out, int out_size)
{
    const float4* a = (const float4*)d_in[0];
    const float4* b = (const float4*)d_in[1];
    const float4* c = (const float4*)d_in[2];
    const int na4 = in_sizes[0] / 4;
    const int nb4 = in_sizes[1] / 4;
    const int nc4 = in_sizes[2] / 4;

    cudaFuncSetAttribute(sum3_tma, cudaFuncAttributeMaxDynamicSharedMemorySize,
                         SMEM_BYTES);
    sum3_tma<<<NBLK, NT, SMEM_BYTES>>>(a, na4, b, nb4, c, nc4, (float*)d_out);
}